// round 11
// baseline (speedup 1.0000x reference)
#include <cuda_runtime.h>
#include <cstdint>

// S5 SSM scan, q-substitution + chunked two-pass form.
//   q_n[t] = a_n*q_n[t-1] + u[t],  y[t] = sum_n (cb*a)_n*q_n[t-1] + (sum cb)*u[t]
// Pass1: chunk-local finals F.  Mid: chain Qin.  Pass2: full scan.
// R10: minimal-shuffle quad reduce (3 SHFL per 4 steps instead of 8) via
// select-based send indices; stage-2 still deferred into next group's compute.

#define D_MODEL   256
#define D_STATE   64
#define SEQ_LEN   4096
#define BATCH     32

#define CH        16
#define CLEN      (SEQ_LEN / CH)          // 256

#define LANES     4
#define SPL       16
#define PACKS     (SPL / 2)               // 8 f32x2 packs
#define TPB       128                     // 32 pairs/block
#define DPB       32                      // d per block
#define TS        64                      // timesteps per smem tile
#define NTILES    (CLEN / TS)             // 4

typedef unsigned long long u64p;

__device__ __forceinline__ u64p pack2(float lo, float hi) {
    u64p r; asm("mov.b64 %0, {%1, %2};" : "=l"(r) : "f"(lo), "f"(hi)); return r;
}
__device__ __forceinline__ void unpack2(u64p v, float& lo, float& hi) {
    asm("mov.b64 {%0, %1}, %2;" : "=f"(lo), "=f"(hi) : "l"(v));
}
__device__ __forceinline__ u64p fma2(u64p a, u64p b, u64p c) {
    u64p d; asm("fma.rn.f32x2 %0, %1, %2, %3;" : "=l"(d) : "l"(a), "l"(b), "l"(c)); return d;
}
__device__ __forceinline__ u64p mul2(u64p a, u64p b) {
    u64p d; asm("mul.rn.f32x2 %0, %1, %2;" : "=l"(d) : "l"(a), "l"(b)); return d;
}
__device__ __forceinline__ u64p add2(u64p a, u64p b) {
    u64p d; asm("add.rn.f32x2 %0, %1, %2;" : "=l"(d) : "l"(a), "l"(b)); return d;
}
__device__ __forceinline__ uint32_t smem_u32(const void* p) {
    return (uint32_t)__cvta_generic_to_shared(p);
}
__device__ __forceinline__ void cp16(uint32_t s, const void* g) {
    asm volatile("cp.async.cg.shared.global [%0], [%1], 16;" :: "r"(s), "l"(g));
}
#define CP_COMMIT() asm volatile("cp.async.commit_group;" ::: "memory")
#define CP_WAIT0()  asm volatile("cp.async.wait_group 0;" ::: "memory")

// 4-way select (3 SELs on the ALU pipe; keeps arrays in registers)
__device__ __forceinline__ float sel4(float a0, float a1, float a2, float a3, int idx) {
    float x = (idx & 1) ? a1 : a0;
    float y = (idx & 1) ? a3 : a2;
    return (idx & 2) ? y : x;
}

__device__ float g_a  [D_MODEL * D_STATE];
__device__ float g_aP [D_MODEL * D_STATE];
__device__ float g_cb [D_MODEL * D_STATE];
__device__ float g_q0 [D_MODEL * D_STATE];
__device__ float g_F  [BATCH * CH * D_MODEL * D_STATE];
__device__ float g_Qin[BATCH * CH * D_MODEL * D_STATE];

__global__ void precomp_kernel(const float* __restrict__ log_dt,
                               const float* __restrict__ A_real,
                               const float* __restrict__ B,
                               const float* __restrict__ C,
                               const float* __restrict__ x0)
{
    int idx = blockIdx.x * blockDim.x + threadIdx.x;
    if (idx >= D_MODEL * D_STATE) return;
    int d = idx / D_STATE;
    float dt = expf(log_dt[d]);
    float Ar = A_real[idx];
    float ad = Ar * dt;
    float a  = expf(ad);
    float bt = (1.0f - a) * B[idx] / Ar;
    float c  = C[idx];
    float cb = c * bt;
    float p0 = c * x0[idx];
    g_a [idx] = a;
    g_aP[idx] = expf(ad * (float)CLEN);
    g_cb[idx] = cb;
    g_q0[idx] = (cb != 0.0f) ? (p0 / cb) : 0.0f;
}

// ---------------- Pass 1: chunk-local finals (recurrence only) --------------
__global__ void __launch_bounds__(TPB, 8)
pass1_kernel(const float* __restrict__ u)
{
    __shared__ float tile[2][TS * DPB];

    int tid  = threadIdx.x;
    int pl   = tid >> 2;
    int sub  = tid & (LANES - 1);

    int blk  = blockIdx.x;
    int dblk = blk & 7;
    int bc   = blk >> 3;
    int c    = bc % (CH - 1);
    int b    = bc / (CH - 1);
    int d    = dblk * DPB + pl;

    u64p a2[PACKS], q2[PACKS];
    int base = d * D_STATE + sub * SPL;
#pragma unroll
    for (int i = 0; i < PACKS; i += 2) {
        float4 av = *reinterpret_cast<const float4*>(g_a + base + 2 * i);
        a2[i]   = pack2(av.x, av.y);
        a2[i+1] = pack2(av.z, av.w);
        q2[i]   = 0ull;
        q2[i+1] = 0ull;
    }

    const float* ubase = u + ((size_t)b * SEQ_LEN + (size_t)c * CLEN) * D_MODEL + dblk * DPB;

#pragma unroll
    for (int k = 0; k < 4; k++) {
        int s  = tid + k * TPB;
        int tl = s >> 3, c4 = (s & 7) * 4;
        cp16(smem_u32(&tile[0][tl * DPB + c4]), ubase + tl * D_MODEL + c4);
    }
    CP_COMMIT();

    for (int ct = 0; ct < NTILES; ct++) {
        CP_WAIT0();
        __syncthreads();
        if (ct + 1 < NTILES) {
            const float* src = ubase + (size_t)(ct + 1) * TS * D_MODEL;
            float* dst = tile[(ct + 1) & 1];
#pragma unroll
            for (int k = 0; k < 4; k++) {
                int s  = tid + k * TPB;
                int tl = s >> 3, c4 = (s & 7) * 4;
                cp16(smem_u32(&dst[tl * DPB + c4]), src + tl * D_MODEL + c4);
            }
            CP_COMMIT();
        }

        const float* tp = tile[ct & 1];
        float uv[2][8];
#pragma unroll
        for (int j = 0; j < 8; j++)
            uv[0][j] = tp[j * DPB + pl];

#pragma unroll
        for (int g = 0; g < TS / 8; g++) {
            int t0 = g * 8;
            float* uvC = uv[g & 1];
            float* uvN = uv[(g + 1) & 1];
            if (g + 1 < TS / 8) {
#pragma unroll
                for (int j = 0; j < 8; j++)
                    uvN[j] = tp[(t0 + 8 + j) * DPB + pl];
            }
#pragma unroll
            for (int j = 0; j < 8; j++) {
                u64p u2 = pack2(uvC[j], uvC[j]);
#pragma unroll
                for (int i = 0; i < PACKS; i++)
                    q2[i] = fma2(a2[i], q2[i], u2);
            }
        }
    }

    float* Fp = g_F + (((size_t)b * CH + c) * D_MODEL + d) * D_STATE + sub * SPL;
#pragma unroll
    for (int i = 0; i < PACKS; i += 2) {
        float4 v;
        unpack2(q2[i],   v.x, v.y);
        unpack2(q2[i+1], v.z, v.w);
        *reinterpret_cast<float4*>(Fp + 2 * i) = v;
    }
}

// ---------------- Middle: chain Qin across chunks ---------------------------
__global__ void __launch_bounds__(256)
mid_kernel()
{
    int idx = blockIdx.x * 256 + threadIdx.x;
    int dn  = idx & (D_MODEL * D_STATE - 1);
    int b   = idx >> 14;

    float aP = g_aP[dn];
    float q  = g_q0[dn];
    size_t stride = (size_t)D_MODEL * D_STATE;
    float* Qp = g_Qin + (size_t)b * CH * stride + dn;
    const float* Fp = g_F + (size_t)b * CH * stride + dn;

    Qp[0] = q;
#pragma unroll
    for (int c = 1; c < CH; c++) {
        q = fmaf(aP, q, Fp[(c - 1) * stride]);
        Qp[c * stride] = q;
    }
}

// ---------------- Pass 2: full scan per chunk -------------------------------
__global__ void __launch_bounds__(TPB, 7)
pass2_kernel(const float* __restrict__ u, float* __restrict__ y)
{
    __shared__ float tile[2][TS * DPB];

    int tid  = threadIdx.x;
    int pl   = tid >> 2;
    int sub  = tid & (LANES - 1);
    int sub1 = sub ^ 1, sub2 = sub ^ 2, sub3 = sub ^ 3;

    int blk  = blockIdx.x;
    int dblk = blk & 7;
    int bc   = blk >> 3;
    int c    = bc & (CH - 1);
    int b    = bc >> 4;
    int d    = dblk * DPB + pl;

    u64p a2[PACKS], cba2[PACKS], q2[PACKS];
    float S = 0.0f;
    int base = d * D_STATE + sub * SPL;
    const float* Qp = g_Qin + (((size_t)b * CH + c) * D_MODEL + d) * D_STATE + sub * SPL;
#pragma unroll
    for (int i = 0; i < PACKS; i += 2) {
        float4 av  = *reinterpret_cast<const float4*>(g_a  + base + 2 * i);
        float4 cbv = *reinterpret_cast<const float4*>(g_cb + base + 2 * i);
        float4 qv  = *reinterpret_cast<const float4*>(Qp + 2 * i);
        a2 [i]    = pack2(av.x,  av.y);   a2 [i+1]  = pack2(av.z,  av.w);
        cba2[i]   = pack2(cbv.x * av.x, cbv.y * av.y);
        cba2[i+1] = pack2(cbv.z * av.z, cbv.w * av.w);
        S += (cbv.x + cbv.y) + (cbv.z + cbv.w);
        q2 [i]    = pack2(qv.x,  qv.y);   q2 [i+1]  = pack2(qv.z,  qv.w);
    }

    const float* ubase = u + ((size_t)b * SEQ_LEN + (size_t)c * CLEN) * D_MODEL + dblk * DPB;
    float*       yp    = y + ((size_t)b * SEQ_LEN + (size_t)c * CLEN) * D_MODEL + d;

#pragma unroll
    for (int k = 0; k < 4; k++) {
        int s  = tid + k * TPB;
        int tl = s >> 3, c4 = (s & 7) * 4;
        cp16(smem_u32(&tile[0][tl * DPB + c4]), ubase + tl * D_MODEL + c4);
    }
    CP_COMMIT();

    // carried pair-sums: pS = pairSum(timestep sub), pS2 = pairSum(timestep sub^2)
    float pS = 0.0f, pS2 = 0.0f;

    for (int ct = 0; ct < NTILES; ct++) {
        CP_WAIT0();
        __syncthreads();
        if (ct + 1 < NTILES) {
            const float* src = ubase + (size_t)(ct + 1) * TS * D_MODEL;
            float* dst = tile[(ct + 1) & 1];
#pragma unroll
            for (int k = 0; k < 4; k++) {
                int s  = tid + k * TPB;
                int tl = s >> 3, c4 = (s & 7) * 4;
                cp16(smem_u32(&dst[tl * DPB + c4]), src + tl * D_MODEL + c4);
            }
            CP_COMMIT();
        }

        const float* tp = tile[ct & 1];
        float uv[2][4];
        float sA[4];

#pragma unroll
        for (int j = 0; j < 4; j++)
            uv[0][j] = tp[j * DPB + pl];

#pragma unroll
        for (int g = 0; g < TS / 4; g++) {
            int t0 = g * 4;
            float* uvC = uv[g & 1];
            float* uvN = uv[(g + 1) & 1];

            // (a) LDS next group (latency hidden by compute)
            if (g + 1 < TS / 4) {
#pragma unroll
                for (int j = 0; j < 4; j++)
                    uvN[j] = tp[(t0 + 4 + j) * DPB + pl];
            }

            // (b) compute steps 0,1
#pragma unroll
            for (int j = 0; j < 2; j++) {
                u64p u2 = pack2(uvC[j], uvC[j]);
                u64p e = mul2(cba2[0], q2[0]);
                u64p o = mul2(cba2[1], q2[1]);
                e = fma2(cba2[2], q2[2], e);
                o = fma2(cba2[3], q2[3], o);
                e = fma2(cba2[4], q2[4], e);
                o = fma2(cba2[5], q2[5], o);
                e = fma2(cba2[6], q2[6], e);
                o = fma2(cba2[7], q2[7], o);
#pragma unroll
                for (int i = 0; i < PACKS; i++)
                    q2[i] = fma2(a2[i], q2[i], u2);
                u64p t = add2(e, o);
                float lo, hi;
                unpack2(t, lo, hi);
                sA[j] = fmaf(S, uvC[j], lo + hi);
            }

            // (c) deferred stage-2 for previous group: 1 shfl.
            //     Partner (lane^2) sends its pairSum(sub^2) == our timestep sub.
            {
                float r2  = __shfl_xor_sync(0xffffffffu, pS2, 2);
                float fin = pS + r2;
                if (ct > 0 || g > 0) {
                    int tpos = (g == 0) ? (ct * TS - 4) : (ct * TS + t0 - 4);
                    __stcs(yp + (tpos + sub) * D_MODEL, fin);
                }
            }

            // (d) compute steps 2,3
#pragma unroll
            for (int j = 2; j < 4; j++) {
                u64p u2 = pack2(uvC[j], uvC[j]);
                u64p e = mul2(cba2[0], q2[0]);
                u64p o = mul2(cba2[1], q2[1]);
                e = fma2(cba2[2], q2[2], e);
                o = fma2(cba2[3], q2[3], o);
                e = fma2(cba2[4], q2[4], e);
                o = fma2(cba2[5], q2[5], o);
                e = fma2(cba2[6], q2[6], e);
                o = fma2(cba2[7], q2[7], o);
#pragma unroll
                for (int i = 0; i < PACKS; i++)
                    q2[i] = fma2(a2[i], q2[i], u2);
                u64p t = add2(e, o);
                float lo, hi;
                unpack2(t, lo, hi);
                sA[j] = fmaf(S, uvC[j], lo + hi);
            }

            // (e) stage-1: 2 shfls.  send sA[sub^1] over xor-1 -> recv sA[sub];
            //     send sA[sub^3] over xor-1 -> recv sA[sub^2].
            {
                float s1 = sel4(sA[0], sA[1], sA[2], sA[3], sub1);
                float s3 = sel4(sA[0], sA[1], sA[2], sA[3], sub3);
                float r1 = __shfl_xor_sync(0xffffffffu, s1, 1);
                float r3 = __shfl_xor_sync(0xffffffffu, s3, 1);
                float pA = sel4(sA[0], sA[1], sA[2], sA[3], sub);
                float pC = sel4(sA[0], sA[1], sA[2], sA[3], sub2);
                pS  = pA + r1;      // pairSum(timestep sub)   over {l, l^1}
                pS2 = pC + r3;      // pairSum(timestep sub^2) over {l, l^1}
            }
        }
    }

    // epilogue: stage-2 + store for the final group of the last tile
    {
        float r2  = __shfl_xor_sync(0xffffffffu, pS2, 2);
        float fin = pS + r2;
        __stcs(yp + (CLEN - 4 + sub) * D_MODEL, fin);
    }
}

extern "C" void kernel_launch(void* const* d_in, const int* in_sizes, int n_in,
                              void* d_out, int out_size)
{
    const float* u      = (const float*)d_in[0];
    const float* log_dt = (const float*)d_in[1];
    const float* A_real = (const float*)d_in[2];
    const float* B      = (const float*)d_in[3];
    const float* C      = (const float*)d_in[4];
    const float* x0     = (const float*)d_in[5];
    float* y = (float*)d_out;

    precomp_kernel<<<(D_MODEL * D_STATE + 255) / 256, 256>>>(log_dt, A_real, B, C, x0);

    int p1_blocks = BATCH * (CH - 1) * (D_MODEL / DPB);    // 3840
    pass1_kernel<<<p1_blocks, TPB>>>(u);

    int mid_threads = BATCH * D_MODEL * D_STATE;           // 524288
    mid_kernel<<<mid_threads / 256, 256>>>();

    int p2_blocks = BATCH * CH * (D_MODEL / DPB);          // 4096
    pass2_kernel<<<p2_blocks, TPB>>>(u, y);
}

// round 12
// speedup vs baseline: 1.0007x; 1.0007x over previous
#include <cuda_runtime.h>
#include <cstdint>

// S5 SSM scan, q-substitution + chunked two-pass form.
//   q_n[t] = a_n*q_n[t-1] + u[t],  y[t] = sum_n (cb*a)_n*q_n[t-1] + (sum cb)*u[t]
// Pass1: chunk-local finals F.  Mid: chain Qin.  Pass2: full scan.
// R10: minimal-shuffle quad reduce (3 SHFL per 4 steps instead of 8) via
// select-based send indices; stage-2 still deferred into next group's compute.

#define D_MODEL   256
#define D_STATE   64
#define SEQ_LEN   4096
#define BATCH     32

#define CH        16
#define CLEN      (SEQ_LEN / CH)          // 256

#define LANES     4
#define SPL       16
#define PACKS     (SPL / 2)               // 8 f32x2 packs
#define TPB       128                     // 32 pairs/block
#define DPB       32                      // d per block
#define TS        64                      // timesteps per smem tile
#define NTILES    (CLEN / TS)             // 4

typedef unsigned long long u64p;

__device__ __forceinline__ u64p pack2(float lo, float hi) {
    u64p r; asm("mov.b64 %0, {%1, %2};" : "=l"(r) : "f"(lo), "f"(hi)); return r;
}
__device__ __forceinline__ void unpack2(u64p v, float& lo, float& hi) {
    asm("mov.b64 {%0, %1}, %2;" : "=f"(lo), "=f"(hi) : "l"(v));
}
__device__ __forceinline__ u64p fma2(u64p a, u64p b, u64p c) {
    u64p d; asm("fma.rn.f32x2 %0, %1, %2, %3;" : "=l"(d) : "l"(a), "l"(b), "l"(c)); return d;
}
__device__ __forceinline__ u64p mul2(u64p a, u64p b) {
    u64p d; asm("mul.rn.f32x2 %0, %1, %2;" : "=l"(d) : "l"(a), "l"(b)); return d;
}
__device__ __forceinline__ u64p add2(u64p a, u64p b) {
    u64p d; asm("add.rn.f32x2 %0, %1, %2;" : "=l"(d) : "l"(a), "l"(b)); return d;
}
__device__ __forceinline__ uint32_t smem_u32(const void* p) {
    return (uint32_t)__cvta_generic_to_shared(p);
}
__device__ __forceinline__ void cp16(uint32_t s, const void* g) {
    asm volatile("cp.async.cg.shared.global [%0], [%1], 16;" :: "r"(s), "l"(g));
}
#define CP_COMMIT() asm volatile("cp.async.commit_group;" ::: "memory")
#define CP_WAIT0()  asm volatile("cp.async.wait_group 0;" ::: "memory")

// 4-way select (3 SELs on the ALU pipe; keeps arrays in registers)
__device__ __forceinline__ float sel4(float a0, float a1, float a2, float a3, int idx) {
    float x = (idx & 1) ? a1 : a0;
    float y = (idx & 1) ? a3 : a2;
    return (idx & 2) ? y : x;
}

__device__ float g_a  [D_MODEL * D_STATE];
__device__ float g_aP [D_MODEL * D_STATE];
__device__ float g_cb [D_MODEL * D_STATE];
__device__ float g_q0 [D_MODEL * D_STATE];
__device__ float g_F  [BATCH * CH * D_MODEL * D_STATE];
__device__ float g_Qin[BATCH * CH * D_MODEL * D_STATE];

__global__ void precomp_kernel(const float* __restrict__ log_dt,
                               const float* __restrict__ A_real,
                               const float* __restrict__ B,
                               const float* __restrict__ C,
                               const float* __restrict__ x0)
{
    int idx = blockIdx.x * blockDim.x + threadIdx.x;
    if (idx >= D_MODEL * D_STATE) return;
    int d = idx / D_STATE;
    float dt = expf(log_dt[d]);
    float Ar = A_real[idx];
    float ad = Ar * dt;
    float a  = expf(ad);
    float bt = (1.0f - a) * B[idx] / Ar;
    float c  = C[idx];
    float cb = c * bt;
    float p0 = c * x0[idx];
    g_a [idx] = a;
    g_aP[idx] = expf(ad * (float)CLEN);
    g_cb[idx] = cb;
    g_q0[idx] = (cb != 0.0f) ? (p0 / cb) : 0.0f;
}

// ---------------- Pass 1: chunk-local finals (recurrence only) --------------
__global__ void __launch_bounds__(TPB, 8)
pass1_kernel(const float* __restrict__ u)
{
    __shared__ float tile[2][TS * DPB];

    int tid  = threadIdx.x;
    int pl   = tid >> 2;
    int sub  = tid & (LANES - 1);

    int blk  = blockIdx.x;
    int dblk = blk & 7;
    int bc   = blk >> 3;
    int c    = bc % (CH - 1);
    int b    = bc / (CH - 1);
    int d    = dblk * DPB + pl;

    u64p a2[PACKS], q2[PACKS];
    int base = d * D_STATE + sub * SPL;
#pragma unroll
    for (int i = 0; i < PACKS; i += 2) {
        float4 av = *reinterpret_cast<const float4*>(g_a + base + 2 * i);
        a2[i]   = pack2(av.x, av.y);
        a2[i+1] = pack2(av.z, av.w);
        q2[i]   = 0ull;
        q2[i+1] = 0ull;
    }

    const float* ubase = u + ((size_t)b * SEQ_LEN + (size_t)c * CLEN) * D_MODEL + dblk * DPB;

#pragma unroll
    for (int k = 0; k < 4; k++) {
        int s  = tid + k * TPB;
        int tl = s >> 3, c4 = (s & 7) * 4;
        cp16(smem_u32(&tile[0][tl * DPB + c4]), ubase + tl * D_MODEL + c4);
    }
    CP_COMMIT();

    for (int ct = 0; ct < NTILES; ct++) {
        CP_WAIT0();
        __syncthreads();
        if (ct + 1 < NTILES) {
            const float* src = ubase + (size_t)(ct + 1) * TS * D_MODEL;
            float* dst = tile[(ct + 1) & 1];
#pragma unroll
            for (int k = 0; k < 4; k++) {
                int s  = tid + k * TPB;
                int tl = s >> 3, c4 = (s & 7) * 4;
                cp16(smem_u32(&dst[tl * DPB + c4]), src + tl * D_MODEL + c4);
            }
            CP_COMMIT();
        }

        const float* tp = tile[ct & 1];
        float uv[2][8];
#pragma unroll
        for (int j = 0; j < 8; j++)
            uv[0][j] = tp[j * DPB + pl];

#pragma unroll
        for (int g = 0; g < TS / 8; g++) {
            int t0 = g * 8;
            float* uvC = uv[g & 1];
            float* uvN = uv[(g + 1) & 1];
            if (g + 1 < TS / 8) {
#pragma unroll
                for (int j = 0; j < 8; j++)
                    uvN[j] = tp[(t0 + 8 + j) * DPB + pl];
            }
#pragma unroll
            for (int j = 0; j < 8; j++) {
                u64p u2 = pack2(uvC[j], uvC[j]);
#pragma unroll
                for (int i = 0; i < PACKS; i++)
                    q2[i] = fma2(a2[i], q2[i], u2);
            }
        }
    }

    float* Fp = g_F + (((size_t)b * CH + c) * D_MODEL + d) * D_STATE + sub * SPL;
#pragma unroll
    for (int i = 0; i < PACKS; i += 2) {
        float4 v;
        unpack2(q2[i],   v.x, v.y);
        unpack2(q2[i+1], v.z, v.w);
        *reinterpret_cast<float4*>(Fp + 2 * i) = v;
    }
}

// ---------------- Middle: chain Qin across chunks ---------------------------
__global__ void __launch_bounds__(256)
mid_kernel()
{
    int idx = blockIdx.x * 256 + threadIdx.x;
    int dn  = idx & (D_MODEL * D_STATE - 1);
    int b   = idx >> 14;

    float aP = g_aP[dn];
    float q  = g_q0[dn];
    size_t stride = (size_t)D_MODEL * D_STATE;
    float* Qp = g_Qin + (size_t)b * CH * stride + dn;
    const float* Fp = g_F + (size_t)b * CH * stride + dn;

    Qp[0] = q;
#pragma unroll
    for (int c = 1; c < CH; c++) {
        q = fmaf(aP, q, Fp[(c - 1) * stride]);
        Qp[c * stride] = q;
    }
}

// ---------------- Pass 2: full scan per chunk -------------------------------
__global__ void __launch_bounds__(TPB, 7)
pass2_kernel(const float* __restrict__ u, float* __restrict__ y)
{
    __shared__ float tile[2][TS * DPB];

    int tid  = threadIdx.x;
    int pl   = tid >> 2;
    int sub  = tid & (LANES - 1);
    int sub1 = sub ^ 1, sub2 = sub ^ 2, sub3 = sub ^ 3;

    int blk  = blockIdx.x;
    int dblk = blk & 7;
    int bc   = blk >> 3;
    int c    = bc & (CH - 1);
    int b    = bc >> 4;
    int d    = dblk * DPB + pl;

    u64p a2[PACKS], cba2[PACKS], q2[PACKS];
    float S = 0.0f;
    int base = d * D_STATE + sub * SPL;
    const float* Qp = g_Qin + (((size_t)b * CH + c) * D_MODEL + d) * D_STATE + sub * SPL;
#pragma unroll
    for (int i = 0; i < PACKS; i += 2) {
        float4 av  = *reinterpret_cast<const float4*>(g_a  + base + 2 * i);
        float4 cbv = *reinterpret_cast<const float4*>(g_cb + base + 2 * i);
        float4 qv  = *reinterpret_cast<const float4*>(Qp + 2 * i);
        a2 [i]    = pack2(av.x,  av.y);   a2 [i+1]  = pack2(av.z,  av.w);
        cba2[i]   = pack2(cbv.x * av.x, cbv.y * av.y);
        cba2[i+1] = pack2(cbv.z * av.z, cbv.w * av.w);
        S += (cbv.x + cbv.y) + (cbv.z + cbv.w);
        q2 [i]    = pack2(qv.x,  qv.y);   q2 [i+1]  = pack2(qv.z,  qv.w);
    }

    const float* ubase = u + ((size_t)b * SEQ_LEN + (size_t)c * CLEN) * D_MODEL + dblk * DPB;
    float*       yp    = y + ((size_t)b * SEQ_LEN + (size_t)c * CLEN) * D_MODEL + d;

#pragma unroll
    for (int k = 0; k < 4; k++) {
        int s  = tid + k * TPB;
        int tl = s >> 3, c4 = (s & 7) * 4;
        cp16(smem_u32(&tile[0][tl * DPB + c4]), ubase + tl * D_MODEL + c4);
    }
    CP_COMMIT();

    // carried pair-sums: pS = pairSum(timestep sub), pS2 = pairSum(timestep sub^2)
    float pS = 0.0f, pS2 = 0.0f;

    for (int ct = 0; ct < NTILES; ct++) {
        CP_WAIT0();
        __syncthreads();
        if (ct + 1 < NTILES) {
            const float* src = ubase + (size_t)(ct + 1) * TS * D_MODEL;
            float* dst = tile[(ct + 1) & 1];
#pragma unroll
            for (int k = 0; k < 4; k++) {
                int s  = tid + k * TPB;
                int tl = s >> 3, c4 = (s & 7) * 4;
                cp16(smem_u32(&dst[tl * DPB + c4]), src + tl * D_MODEL + c4);
            }
            CP_COMMIT();
        }

        const float* tp = tile[ct & 1];
        float uv[2][4];
        float sA[4];

#pragma unroll
        for (int j = 0; j < 4; j++)
            uv[0][j] = tp[j * DPB + pl];

#pragma unroll
        for (int g = 0; g < TS / 4; g++) {
            int t0 = g * 4;
            float* uvC = uv[g & 1];
            float* uvN = uv[(g + 1) & 1];

            // (a) LDS next group (latency hidden by compute)
            if (g + 1 < TS / 4) {
#pragma unroll
                for (int j = 0; j < 4; j++)
                    uvN[j] = tp[(t0 + 4 + j) * DPB + pl];
            }

            // (b) compute steps 0,1
#pragma unroll
            for (int j = 0; j < 2; j++) {
                u64p u2 = pack2(uvC[j], uvC[j]);
                u64p e = mul2(cba2[0], q2[0]);
                u64p o = mul2(cba2[1], q2[1]);
                e = fma2(cba2[2], q2[2], e);
                o = fma2(cba2[3], q2[3], o);
                e = fma2(cba2[4], q2[4], e);
                o = fma2(cba2[5], q2[5], o);
                e = fma2(cba2[6], q2[6], e);
                o = fma2(cba2[7], q2[7], o);
#pragma unroll
                for (int i = 0; i < PACKS; i++)
                    q2[i] = fma2(a2[i], q2[i], u2);
                u64p t = add2(e, o);
                float lo, hi;
                unpack2(t, lo, hi);
                sA[j] = fmaf(S, uvC[j], lo + hi);
            }

            // (c) deferred stage-2 for previous group: 1 shfl.
            //     Partner (lane^2) sends its pairSum(sub^2) == our timestep sub.
            {
                float r2  = __shfl_xor_sync(0xffffffffu, pS2, 2);
                float fin = pS + r2;
                if (ct > 0 || g > 0) {
                    int tpos = (g == 0) ? (ct * TS - 4) : (ct * TS + t0 - 4);
                    __stcs(yp + (tpos + sub) * D_MODEL, fin);
                }
            }

            // (d) compute steps 2,3
#pragma unroll
            for (int j = 2; j < 4; j++) {
                u64p u2 = pack2(uvC[j], uvC[j]);
                u64p e = mul2(cba2[0], q2[0]);
                u64p o = mul2(cba2[1], q2[1]);
                e = fma2(cba2[2], q2[2], e);
                o = fma2(cba2[3], q2[3], o);
                e = fma2(cba2[4], q2[4], e);
                o = fma2(cba2[5], q2[5], o);
                e = fma2(cba2[6], q2[6], e);
                o = fma2(cba2[7], q2[7], o);
#pragma unroll
                for (int i = 0; i < PACKS; i++)
                    q2[i] = fma2(a2[i], q2[i], u2);
                u64p t = add2(e, o);
                float lo, hi;
                unpack2(t, lo, hi);
                sA[j] = fmaf(S, uvC[j], lo + hi);
            }

            // (e) stage-1: 2 shfls.  send sA[sub^1] over xor-1 -> recv sA[sub];
            //     send sA[sub^3] over xor-1 -> recv sA[sub^2].
            {
                float s1 = sel4(sA[0], sA[1], sA[2], sA[3], sub1);
                float s3 = sel4(sA[0], sA[1], sA[2], sA[3], sub3);
                float r1 = __shfl_xor_sync(0xffffffffu, s1, 1);
                float r3 = __shfl_xor_sync(0xffffffffu, s3, 1);
                float pA = sel4(sA[0], sA[1], sA[2], sA[3], sub);
                float pC = sel4(sA[0], sA[1], sA[2], sA[3], sub2);
                pS  = pA + r1;      // pairSum(timestep sub)   over {l, l^1}
                pS2 = pC + r3;      // pairSum(timestep sub^2) over {l, l^1}
            }
        }
    }

    // epilogue: stage-2 + store for the final group of the last tile
    {
        float r2  = __shfl_xor_sync(0xffffffffu, pS2, 2);
        float fin = pS + r2;
        __stcs(yp + (CLEN - 4 + sub) * D_MODEL, fin);
    }
}

extern "C" void kernel_launch(void* const* d_in, const int* in_sizes, int n_in,
                              void* d_out, int out_size)
{
    const float* u      = (const float*)d_in[0];
    const float* log_dt = (const float*)d_in[1];
    const float* A_real = (const float*)d_in[2];
    const float* B      = (const float*)d_in[3];
    const float* C      = (const float*)d_in[4];
    const float* x0     = (const float*)d_in[5];
    float* y = (float*)d_out;

    precomp_kernel<<<(D_MODEL * D_STATE + 255) / 256, 256>>>(log_dt, A_real, B, C, x0);

    int p1_blocks = BATCH * (CH - 1) * (D_MODEL / DPB);    // 3840
    pass1_kernel<<<p1_blocks, TPB>>>(u);

    int mid_threads = BATCH * D_MODEL * D_STATE;           // 524288
    mid_kernel<<<mid_threads / 256, 256>>>();

    int p2_blocks = BATCH * CH * (D_MODEL / DPB);          // 4096
    pass2_kernel<<<p2_blocks, TPB>>>(u, y);
}